// round 1
// baseline (speedup 1.0000x reference)
#include <cuda_runtime.h>
#include <cstdint>

// Problem constants
#define S_LEN 256
#define B_DIM 128
#define M_TOT (S_LEN * B_DIM)   // 32768 rows (m = s*128 + b)
#define N_TOT 2048               // branch1 cols [0,1024), branch2 [1024,2048)
#define K_TOT 1024

// Scratch (device globals; no allocation allowed)
__device__ float g_C[B_DIM * N_TOT];  // per-batch bias table: f@W_bot + b
__device__ float g_s[2 * M_TOT];      // logits s1, s2

__device__ __forceinline__ uint32_t f2tf32(float x) {
    uint32_t u;
    asm("cvt.rna.tf32.f32 %0, %1;" : "=r"(u) : "f"(x));
    return u;
}

__device__ __forceinline__ void mma_tf32(float c[4], uint32_t a0, uint32_t a1,
                                         uint32_t a2, uint32_t a3,
                                         uint32_t b0, uint32_t b1) {
    asm volatile(
        "mma.sync.aligned.m16n8k8.row.col.f32.tf32.tf32.f32 "
        "{%0,%1,%2,%3}, {%4,%5,%6,%7}, {%8,%9}, {%0,%1,%2,%3};\n"
        : "+f"(c[0]), "+f"(c[1]), "+f"(c[2]), "+f"(c[3])
        : "r"(a0), "r"(a1), "r"(a2), "r"(a3), "r"(b0), "r"(b1));
}

// ---------------------------------------------------------------------------
// Kernel A: C[b, j] = bias[j] + sum_k f[b,k] * W_bot[k, j]   (plus zero g_s)
// grid 64 blocks (32 cols each), 256 threads
// ---------------------------------------------------------------------------
__global__ __launch_bounds__(256) void prep_kernel(
    const float* __restrict__ f1, const float* __restrict__ f2,
    const float* __restrict__ W11, const float* __restrict__ W12,
    const float* __restrict__ b11, const float* __restrict__ b12) {
    // zero the logit scratch (graph replays rerun this every launch)
    for (int i = blockIdx.x * 256 + threadIdx.x; i < 2 * M_TOT; i += 64 * 256)
        g_s[i] = 0.0f;

    __shared__ __align__(16) float Fs[128][68];
    __shared__ __align__(16) float Ws[64][36];

    int tid = threadIdx.x;
    int jt = blockIdx.x;            // 0..63
    int branch = (jt >= 32);
    int j0g = jt * 32;              // global col in [0,2048)
    int j0 = j0g & 1023;            // col within branch
    const float* F = branch ? f2 : f1;
    const float* W = (branch ? W12 : W11) + 1024 * 1024;  // bottom half rows
    const float* bias = branch ? b12 : b11;

    float acc[4][4] = {};
    int tr = tid >> 3, tc = tid & 7;
    int r0 = tr * 4, c0 = tc * 4;

    for (int k0 = 0; k0 < 1024; k0 += 64) {
#pragma unroll
        for (int p = 0; p < 8; p++) {
            int idx = tid + p * 256;
            int r = idx >> 4, c = idx & 15;
            *(float4*)&Fs[r][c * 4] = *(const float4*)(F + r * 1024 + k0 + c * 4);
        }
#pragma unroll
        for (int p = 0; p < 2; p++) {
            int idx = tid + p * 256;
            int r = idx >> 3, c = idx & 7;
            *(float4*)&Ws[r][c * 4] =
                *(const float4*)(W + (k0 + r) * 1024 + j0 + c * 4);
        }
        __syncthreads();
#pragma unroll 8
        for (int k = 0; k < 64; k++) {
            float fr[4], wc[4];
#pragma unroll
            for (int i = 0; i < 4; i++) fr[i] = Fs[r0 + i][k];
#pragma unroll
            for (int j = 0; j < 4; j++) wc[j] = Ws[k][c0 + j];
#pragma unroll
            for (int i = 0; i < 4; i++)
#pragma unroll
                for (int j = 0; j < 4; j++) acc[i][j] = fmaf(fr[i], wc[j], acc[i][j]);
        }
        __syncthreads();
    }
#pragma unroll
    for (int i = 0; i < 4; i++)
#pragma unroll
        for (int j = 0; j < 4; j++)
            g_C[(r0 + i) * 2048 + j0g + c0 + j] = acc[i][j] + bias[j0 + c0 + j];
}

// ---------------------------------------------------------------------------
// Kernel B: fused GEMM + tanh-dot epilogue -> logits
//   G[m, n] = sum_k seq[m,k] * Wtop[k, n]     (tf32 mma, fp32 accum)
//   s[branch][m] += sum_n tanh(G + C[b,n]) * W2[n]
// grid (256 Mblocks, 16 Nblocks), 256 threads (8 warps, 2x4), tile 128x128x32
// ---------------------------------------------------------------------------
__global__ __launch_bounds__(256) void main_kernel(
    const float* __restrict__ seq,
    const float* __restrict__ W11, const float* __restrict__ W12,
    const float* __restrict__ W21, const float* __restrict__ W22) {
    __shared__ __align__(16) uint32_t As[128][36];  // [m][k], stride 36 -> conflict-free frags
    __shared__ __align__(16) uint32_t Bs[32][132];  // [k][n]
    __shared__ float red[128][4];

    int tid = threadIdx.x;
    int lane = tid & 31, warp = tid >> 5;
    int wm = warp >> 2, wn = warp & 3;
    int m0 = blockIdx.x * 128;
    int nb = blockIdx.y;
    int branch = nb >> 3;
    int n0g = nb * 128;
    int ncol0 = n0g & 1023;
    const float* Bsrc = branch ? W12 : W11;  // top rows (k < 1024)
    const float* Wv = branch ? W22 : W21;
    float* sOut = g_s + branch * M_TOT;

    float acc[4][4][4] = {};

    float4 aR[4], bR[4];

    auto loadA = [&](int k0, float4* a) {
#pragma unroll
        for (int p = 0; p < 4; p++) {
            int idx = tid + p * 256;
            int r = idx >> 3, c = idx & 7;
            a[p] = *(const float4*)(seq + (m0 + r) * 1024 + k0 + c * 4);
        }
    };
    auto loadB = [&](int k0, float4* b) {
#pragma unroll
        for (int p = 0; p < 4; p++) {
            int idx = tid + p * 256;
            int r = idx >> 5, c = idx & 31;
            b[p] = *(const float4*)(Bsrc + (k0 + r) * 1024 + ncol0 + c * 4);
        }
    };
    auto storeTiles = [&](const float4* a, const float4* b) {
#pragma unroll
        for (int p = 0; p < 4; p++) {
            int idx = tid + p * 256;
            int r = idx >> 3, c = idx & 7;
            uint4 u;
            u.x = f2tf32(a[p].x); u.y = f2tf32(a[p].y);
            u.z = f2tf32(a[p].z); u.w = f2tf32(a[p].w);
            *(uint4*)&As[r][c * 4] = u;
            int r2 = idx >> 5, c2 = idx & 31;
            uint4 v;
            v.x = f2tf32(b[p].x); v.y = f2tf32(b[p].y);
            v.z = f2tf32(b[p].z); v.w = f2tf32(b[p].w);
            *(uint4*)&Bs[r2][c2 * 4] = v;
        }
    };

    loadA(0, aR);
    loadB(0, bR);
    storeTiles(aR, bR);
    __syncthreads();

    int r = lane >> 2, c = lane & 3;
    for (int t = 0; t < 32; t++) {
        float4 aN[4], bN[4];
        if (t < 31) {
            loadA((t + 1) * 32, aN);
            loadB((t + 1) * 32, bN);
        }
#pragma unroll
        for (int kk = 0; kk < 4; kk++) {
            int kb = kk * 8;
            uint32_t af[4][4], bf[4][2];
#pragma unroll
            for (int mf = 0; mf < 4; mf++) {
                int m = wm * 64 + mf * 16 + r;
                af[mf][0] = As[m][kb + c];
                af[mf][1] = As[m + 8][kb + c];
                af[mf][2] = As[m][kb + c + 4];
                af[mf][3] = As[m + 8][kb + c + 4];
            }
#pragma unroll
            for (int nf = 0; nf < 4; nf++) {
                int n = wn * 32 + nf * 8 + r;
                bf[nf][0] = Bs[kb + c][n];
                bf[nf][1] = Bs[kb + c + 4][n];
            }
#pragma unroll
            for (int mf = 0; mf < 4; mf++)
#pragma unroll
                for (int nf = 0; nf < 4; nf++)
                    mma_tf32(acc[mf][nf], af[mf][0], af[mf][1], af[mf][2],
                             af[mf][3], bf[nf][0], bf[nf][1]);
        }
        __syncthreads();
        if (t < 31) {
            storeTiles(aN, bN);
            __syncthreads();
        }
    }

    // Epilogue: tanh(G + C) * W2, reduce over the 128 cols of this block
    int c2 = (lane & 3) * 2;
    float wvv[4][2];
#pragma unroll
    for (int nf = 0; nf < 4; nf++) {
        wvv[nf][0] = Wv[ncol0 + wn * 32 + nf * 8 + c2];
        wvv[nf][1] = Wv[ncol0 + wn * 32 + nf * 8 + c2 + 1];
    }
    float rs0[4] = {}, rs1[4] = {};
#pragma unroll
    for (int mf = 0; mf < 4; mf++) {
        int row0 = wm * 64 + mf * 16 + r;  // row-in-block == batch index b
        const float* C0 = g_C + row0 * 2048 + n0g + wn * 32;
        const float* C1 = g_C + (row0 + 8) * 2048 + n0g + wn * 32;
#pragma unroll
        for (int nf = 0; nf < 4; nf++) {
            int off = nf * 8 + c2;
            float t0 = tanhf(acc[mf][nf][0] + C0[off]);
            float t1 = tanhf(acc[mf][nf][1] + C0[off + 1]);
            float t2 = tanhf(acc[mf][nf][2] + C1[off]);
            float t3 = tanhf(acc[mf][nf][3] + C1[off + 1]);
            rs0[mf] = fmaf(t0, wvv[nf][0], rs0[mf]);
            rs0[mf] = fmaf(t1, wvv[nf][1], rs0[mf]);
            rs1[mf] = fmaf(t2, wvv[nf][0], rs1[mf]);
            rs1[mf] = fmaf(t3, wvv[nf][1], rs1[mf]);
        }
    }
#pragma unroll
    for (int mf = 0; mf < 4; mf++) {
        rs0[mf] += __shfl_xor_sync(0xffffffffu, rs0[mf], 1);
        rs0[mf] += __shfl_xor_sync(0xffffffffu, rs0[mf], 2);
        rs1[mf] += __shfl_xor_sync(0xffffffffu, rs1[mf], 1);
        rs1[mf] += __shfl_xor_sync(0xffffffffu, rs1[mf], 2);
    }
    if ((lane & 3) == 0) {
#pragma unroll
        for (int mf = 0; mf < 4; mf++) {
            red[wm * 64 + mf * 16 + r][wn] = rs0[mf];
            red[wm * 64 + mf * 16 + r + 8][wn] = rs1[mf];
        }
    }
    __syncthreads();
    if (tid < 128) {
        float s = red[tid][0] + red[tid][1] + red[tid][2] + red[tid][3];
        atomicAdd(&sOut[m0 + tid], s);
    }
}

// ---------------------------------------------------------------------------
// Kernel D: per-b dual softmax over S (recomputed per block, cheap) + weighted
// reduction out[b,d] = sum_s a[s]*seq[s,b,d].  grid (128 b, 4 d-chunks), 256 thr
// ---------------------------------------------------------------------------
__global__ __launch_bounds__(256) void finalize_kernel(
    const float* __restrict__ seq, float* __restrict__ out) {
    __shared__ float aw[256];
    __shared__ float sbuf[16];
    int b = blockIdx.x;
    int tid = threadIdx.x;
    int lane = tid & 31, warp = tid >> 5;

    float v1 = g_s[tid * 128 + b];
    float v2 = g_s[M_TOT + tid * 128 + b];

    float m1 = v1, m2 = v2;
#pragma unroll
    for (int o = 16; o; o >>= 1) {
        m1 = fmaxf(m1, __shfl_xor_sync(0xffffffffu, m1, o));
        m2 = fmaxf(m2, __shfl_xor_sync(0xffffffffu, m2, o));
    }
    if (lane == 0) { sbuf[warp] = m1; sbuf[8 + warp] = m2; }
    __syncthreads();
    m1 = sbuf[0]; m2 = sbuf[8];
#pragma unroll
    for (int i = 1; i < 8; i++) {
        m1 = fmaxf(m1, sbuf[i]);
        m2 = fmaxf(m2, sbuf[8 + i]);
    }
    float e1 = __expf(v1 - m1), e2 = __expf(v2 - m2);
    __syncthreads();  // sbuf reuse
    float s1 = e1, s2 = e2;
#pragma unroll
    for (int o = 16; o; o >>= 1) {
        s1 += __shfl_xor_sync(0xffffffffu, s1, o);
        s2 += __shfl_xor_sync(0xffffffffu, s2, o);
    }
    if (lane == 0) { sbuf[warp] = s1; sbuf[8 + warp] = s2; }
    __syncthreads();
    s1 = 0.0f; s2 = 0.0f;
#pragma unroll
    for (int i = 0; i < 8; i++) { s1 += sbuf[i]; s2 += sbuf[8 + i]; }
    aw[tid] = (e1 / s1 + e2 / s2) * (0.5f / 256.0f);
    __syncthreads();

    int d = blockIdx.y * 256 + tid;
    const float* p = seq + b * 1024 + d;
    float acc = 0.0f;
#pragma unroll 8
    for (int s = 0; s < 256; s++) acc = fmaf(aw[s], p[s * 131072], acc);
    out[b * 1024 + d] = acc;
}

// ---------------------------------------------------------------------------
extern "C" void kernel_launch(void* const* d_in, const int* in_sizes, int n_in,
                              void* d_out, int out_size) {
    const float* f1  = (const float*)d_in[0];
    const float* f2  = (const float*)d_in[1];
    const float* seq = (const float*)d_in[2];
    const float* W11 = (const float*)d_in[3];
    const float* b11 = (const float*)d_in[4];
    const float* W12 = (const float*)d_in[5];
    const float* b12 = (const float*)d_in[6];
    const float* W21 = (const float*)d_in[7];
    // d_in[8] = b21, d_in[10] = b22: scalar shifts, softmax-invariant -> unused
    const float* W22 = (const float*)d_in[9];
    float* out = (float*)d_out;

    prep_kernel<<<64, 256>>>(f1, f2, W11, W12, b11, b12);
    main_kernel<<<dim3(256, 16), 256>>>(seq, W11, W12, W21, W22);
    finalize_kernel<<<dim3(128, 4), 256>>>(seq, out);
}

// round 5
// speedup vs baseline: 2.1675x; 2.1675x over previous
#include <cuda_runtime.h>
#include <cuda_fp16.h>
#include <cstdint>

// ---------------------------------------------------------------------------
// Problem constants: S=256, B=128, D=1024, m = s*128 + b (so m % 128 == b)
// ---------------------------------------------------------------------------
#define M_TOT 32768
#define N_TOT 2048
#define K_TOT 1024

// Device scratch (static; no allocation allowed)
__device__ __align__(256) __half g_seqh[(size_t)M_TOT * 1024];   // fp16 copy of seq
__device__ __align__(256) __half g_WTh[(size_t)N_TOT * 1024];    // [n][k] W_top^T fp16
__device__ __align__(256) float g_Ct[N_TOT * 128];               // [n][b] bias + F@W_bot
__device__ float g_s[2 * M_TOT];                                 // logits

// ---------------------------------------------------------------------------
// Helpers
// ---------------------------------------------------------------------------
__device__ __forceinline__ uint32_t smem_u32(const void* p) {
    uint32_t a;
    asm("{ .reg .u64 t; cvta.to.shared.u64 t, %1; cvt.u32.u64 %0, t; }" : "=r"(a) : "l"(p));
    return a;
}
__device__ __forceinline__ float tanh_ap(float x) {
    float y;
    asm("tanh.approx.f32 %0, %1;" : "=f"(y) : "f"(x));
    return y;
}
__device__ __forceinline__ void cp16(uint32_t dst, const void* src) {
    asm volatile("cp.async.cg.shared.global [%0], [%1], 16;" :: "r"(dst), "l"(src) : "memory");
}
#define CP_COMMIT() asm volatile("cp.async.commit_group;" ::: "memory")
#define CP_WAIT(n) asm volatile("cp.async.wait_group %0;" :: "n"(n) : "memory")

__device__ __forceinline__ void ldsm4(uint32_t& r0, uint32_t& r1, uint32_t& r2,
                                      uint32_t& r3, uint32_t addr) {
    asm volatile("ldmatrix.sync.aligned.m8n8.x4.shared.b16 {%0,%1,%2,%3}, [%4];"
                 : "=r"(r0), "=r"(r1), "=r"(r2), "=r"(r3) : "r"(addr));
}
__device__ __forceinline__ void mma16816(float c[4], uint32_t a0, uint32_t a1,
                                         uint32_t a2, uint32_t a3, uint32_t b0,
                                         uint32_t b1) {
    asm volatile(
        "mma.sync.aligned.m16n8k16.row.col.f32.f16.f16.f32 "
        "{%0,%1,%2,%3},{%4,%5,%6,%7},{%8,%9},{%0,%1,%2,%3};"
        : "+f"(c[0]), "+f"(c[1]), "+f"(c[2]), "+f"(c[3])
        : "r"(a0), "r"(a1), "r"(a2), "r"(a3), "r"(b0), "r"(b1));
}

// ---------------------------------------------------------------------------
// Kernel 0: convert seq fp32 -> fp16 (g_seqh). grid 2048 x 256
// ---------------------------------------------------------------------------
__global__ __launch_bounds__(256) void convert_kernel(const float* __restrict__ seq) {
    const float4* src = (const float4*)seq;
    uint2* dst = (uint2*)g_seqh;
    size_t i0 = (size_t)blockIdx.x * 256 + threadIdx.x;
    for (size_t p = i0; p < 8388608ull; p += 524288ull) {
        float4 v = src[p];
        __half2 h0 = __floats2half2_rn(v.x, v.y);
        __half2 h1 = __floats2half2_rn(v.z, v.w);
        dst[p] = make_uint2(*(uint32_t*)&h0, *(uint32_t*)&h1);
    }
}

// ---------------------------------------------------------------------------
// Kernel 1: transpose W_top -> g_WTh[n][k] fp16; also zero g_s and init
// g_Ct[n][b] = bias[n].  grid (32 k-tiles, 64 n-tiles) x 256
// ---------------------------------------------------------------------------
__global__ __launch_bounds__(256) void transpose_kernel(
    const float* __restrict__ W11, const float* __restrict__ W12,
    const float* __restrict__ b11, const float* __restrict__ b12) {
    __shared__ float T[32][33];
    int tid = threadIdx.x;
    int lin = blockIdx.y * 32 + blockIdx.x;  // 0..2047
    if (lin < 256) g_s[lin * 256 + tid] = 0.0f;
    if (lin < 1024) {
        int idx = lin * 256 + tid;           // < 262144
        int n = idx >> 7;
        g_Ct[idx] = (n < 1024) ? b11[n] : b12[n - 1024];
    }

    int r0 = blockIdx.x * 32;                // k rows [0,1024)
    int branch = blockIdx.y >> 5;
    int n0loc = (blockIdx.y & 31) * 32;
    int n0g = branch * 1024 + n0loc;
    const float* W = branch ? W12 : W11;     // top rows k<1024

    int j = tid & 31, i0 = (tid >> 5) * 4;
#pragma unroll
    for (int ii = 0; ii < 4; ii++)
        T[i0 + ii][j] = W[(size_t)(r0 + i0 + ii) * 1024 + n0loc + j];
    __syncthreads();
#pragma unroll
    for (int ii = 0; ii < 4; ii++)
        g_WTh[(size_t)(n0g + i0 + ii) * 1024 + r0 + j] = __float2half_rn(T[j][i0 + ii]);
}

// ---------------------------------------------------------------------------
// Kernel 2: g_Ct[n][b] += sum_k F[b,k] * W_bot[k,n]  (fp32, 4-way k-split)
// grid 256 = 64 col-tiles x 4 k-splits, 256 threads
// ---------------------------------------------------------------------------
__global__ __launch_bounds__(256) void prepc_kernel(
    const float* __restrict__ f1, const float* __restrict__ f2,
    const float* __restrict__ W11, const float* __restrict__ W12) {
    __shared__ __align__(16) float Fs[128][68];
    __shared__ __align__(16) float Ws[64][36];

    int tid = threadIdx.x;
    int ct = blockIdx.x & 63;
    int ks = blockIdx.x >> 6;          // 0..3, k range [ks*256, ks*256+256)
    int branch = (ct >= 32);
    int j0g = ct * 32;
    int j0 = j0g & 1023;
    const float* F = (branch ? f2 : f1) + ks * 256;
    const float* W = (branch ? W12 : W11) + (size_t)(1024 + ks * 256) * 1024;

    float acc[4][4] = {};
    int tr = tid >> 3, tc = tid & 7;
    int r0 = tr * 4, c0 = tc * 4;

    for (int k0 = 0; k0 < 256; k0 += 64) {
#pragma unroll
        for (int p = 0; p < 8; p++) {
            int idx = tid + p * 256;
            int r = idx >> 4, c = idx & 15;
            *(float4*)&Fs[r][c * 4] = *(const float4*)(F + (size_t)r * 1024 + k0 + c * 4);
        }
#pragma unroll
        for (int p = 0; p < 2; p++) {
            int idx = tid + p * 256;
            int r = idx >> 3, c = idx & 7;
            *(float4*)&Ws[r][c * 4] = *(const float4*)(W + (size_t)(k0 + r) * 1024 + j0 + c * 4);
        }
        __syncthreads();
#pragma unroll 8
        for (int k = 0; k < 64; k++) {
            float fr[4], wc[4];
#pragma unroll
            for (int i = 0; i < 4; i++) fr[i] = Fs[r0 + i][k];
#pragma unroll
            for (int j = 0; j < 4; j++) wc[j] = Ws[k][c0 + j];
#pragma unroll
            for (int i = 0; i < 4; i++)
#pragma unroll
                for (int j = 0; j < 4; j++) acc[i][j] = fmaf(fr[i], wc[j], acc[i][j]);
        }
        __syncthreads();
    }
#pragma unroll
    for (int i = 0; i < 4; i++)
#pragma unroll
        for (int j = 0; j < 4; j++)
            atomicAdd(&g_Ct[(j0g + c0 + j) * 128 + r0 + i], acc[i][j]);
}

// ---------------------------------------------------------------------------
// Kernel 3: fp16 mma.sync GEMM (tile 128m x 256n, KC=32, 3-stage cp.async)
// + fused tanh-dot epilogue -> logits.  grid (8 nbt, 256 mb) x 256 threads
// warp grid 2x4: warp tile 64m x 64n
// ---------------------------------------------------------------------------
#define AST 10240          // A stage bytes: 128 rows * 80B (32 halves + pad)
#define BST 20480          // B stage bytes: 256 rows * 80B
#define SM_BS 30720        // Bs base (3 A stages first)
#define SM_W2 92160
#define SM_RED 93184
#define SMEM_MAIN 95232

__global__ __launch_bounds__(256, 1) void main_kernel(
    const float* __restrict__ W21, const float* __restrict__ W22) {
    extern __shared__ __align__(128) uint8_t smem[];
    uint32_t sb = smem_u32(smem);
    int tid = threadIdx.x;
    int lane = tid & 31, warp = tid >> 5;
    int wm = warp >> 2, wn = warp & 3;

    int nbt = blockIdx.x;          // 0..7
    int mb = blockIdx.y;           // 0..255
    int m0 = mb * 128;
    int n0g = nbt * 256;
    int branch = nbt >> 2;
    int ncol0 = n0g & 1023;

    // cp.async source/dest precompute
    const __half* Asrc = g_seqh + (size_t)m0 * 1024;
    const __half* Bsrc = g_WTh + (size_t)n0g * 1024;

    auto issueStage = [&](int k0, int slot) {
#pragma unroll
        for (int p = 0; p < 2; p++) {
            int c = tid + p * 256;
            int m = c >> 2, kq = c & 3;
            cp16(sb + slot * AST + m * 80 + kq * 16,
                 Asrc + (size_t)m * 1024 + k0 + kq * 8);
        }
#pragma unroll
        for (int p = 0; p < 4; p++) {
            int c = tid + p * 256;
            int n = c >> 2, kq = c & 3;
            cp16(sb + SM_BS + slot * BST + n * 80 + kq * 16,
                 Bsrc + (size_t)n * 1024 + k0 + kq * 8);
        }
        CP_COMMIT();
    };

    issueStage(0, 0);
    issueStage(32, 1);
    issueStage(64, 2);

    float acc[4][8][4] = {};

    // fragment address components (bytes)
    uint32_t aFrag = (uint32_t)((wm * 64 + (lane & 7) + ((lane >> 3) & 1) * 8) * 80 +
                                (lane >> 4) * 16);
    uint32_t bFrag = (uint32_t)(((lane & 7) + (lane >> 4) * 8) * 80 +
                                ((lane >> 3) & 1) * 16);

    for (int it = 0; it < 32; it++) {
        CP_WAIT(2);
        __syncthreads();
        int slot = it - (it / 3) * 3;  // it % 3
        uint32_t aB = sb + slot * AST + aFrag;
        uint32_t bB = sb + SM_BS + slot * BST + bFrag + wn * 64 * 80;
#pragma unroll
        for (int ksx = 0; ksx < 2; ksx++) {
            uint32_t af[4][4], bf[4][4];
#pragma unroll
            for (int mf = 0; mf < 4; mf++)
                ldsm4(af[mf][0], af[mf][1], af[mf][2], af[mf][3],
                      aB + mf * 16 * 80 + ksx * 32);
#pragma unroll
            for (int p = 0; p < 4; p++)
                ldsm4(bf[p][0], bf[p][1], bf[p][2], bf[p][3],
                      bB + p * 16 * 80 + ksx * 32);
#pragma unroll
            for (int mf = 0; mf < 4; mf++)
#pragma unroll
                for (int nf = 0; nf < 8; nf++) {
                    int p = nf >> 1;
                    if (nf & 1)
                        mma16816(acc[mf][nf], af[mf][0], af[mf][1], af[mf][2],
                                 af[mf][3], bf[p][2], bf[p][3]);
                    else
                        mma16816(acc[mf][nf], af[mf][0], af[mf][1], af[mf][2],
                                 af[mf][3], bf[p][0], bf[p][1]);
                }
        }
        __syncthreads();
        if (it + 3 < 32) issueStage((it + 3) * 32, slot);
    }

    // ---- epilogue: s[m] += sum_n tanh(G + Ct[n][b]) * W2[n] ----
    CP_WAIT(0);
    __syncthreads();
    float* W2s = (float*)(smem + SM_W2);
    const float* Wv = branch ? W22 : W21;
    W2s[tid] = Wv[ncol0 + tid];   // 256 cols, 256 threads
    float* CtS = (float*)smem;    // [128 n][132 pad] fp32, overlays GEMM bufs
    float* red = (float*)(smem + SM_RED);

    int gr = lane >> 2, qc = (lane & 3) * 2;
    float rs0[4] = {}, rs1[4] = {};

#pragma unroll
    for (int h = 0; h < 2; h++) {
        __syncthreads();
        for (int i = tid; i < 4096; i += 256) {
            int n = i >> 5, b4 = i & 31;
            *(float4*)&CtS[n * 132 + b4 * 4] =
                *(const float4*)&g_Ct[(n0g + h * 128 + n) * 128 + b4 * 4];
        }
        __syncthreads();
        if ((wn >> 1) == h) {
#pragma unroll
            for (int mf = 0; mf < 4; mf++) {
                int r0l = wm * 64 + mf * 16 + gr;
#pragma unroll
                for (int nf = 0; nf < 8; nf++) {
                    int lc = (wn & 1) * 64 + nf * 8 + qc;  // col within 128-half
                    int gc = wn * 64 + nf * 8 + qc;        // col within 256-tile
                    float w0 = W2s[gc], w1 = W2s[gc + 1];
                    const float* Cc0 = &CtS[lc * 132];
                    const float* Cc1 = &CtS[(lc + 1) * 132];
                    rs0[mf] += tanh_ap(acc[mf][nf][0] + Cc0[r0l]) * w0 +
                               tanh_ap(acc[mf][nf][1] + Cc1[r0l]) * w1;
                    rs1[mf] += tanh_ap(acc[mf][nf][2] + Cc0[r0l + 8]) * w0 +
                               tanh_ap(acc[mf][nf][3] + Cc1[r0l + 8]) * w1;
                }
            }
        }
    }
    __syncthreads();
#pragma unroll
    for (int mf = 0; mf < 4; mf++) {
        rs0[mf] += __shfl_xor_sync(0xffffffffu, rs0[mf], 1);
        rs0[mf] += __shfl_xor_sync(0xffffffffu, rs0[mf], 2);
        rs1[mf] += __shfl_xor_sync(0xffffffffu, rs1[mf], 1);
        rs1[mf] += __shfl_xor_sync(0xffffffffu, rs1[mf], 2);
    }
    if ((lane & 3) == 0) {
#pragma unroll
        for (int mf = 0; mf < 4; mf++) {
            int r0l = wm * 64 + mf * 16 + gr;
            red[r0l * 4 + wn] = rs0[mf];
            red[(r0l + 8) * 4 + wn] = rs1[mf];
        }
    }
    __syncthreads();
    if (tid < 128) {
        float sv = red[tid * 4] + red[tid * 4 + 1] + red[tid * 4 + 2] + red[tid * 4 + 3];
        atomicAdd(&g_s[branch * M_TOT + m0 + tid], sv);
    }
}

// ---------------------------------------------------------------------------
// Kernel 4: dual softmax over S + weighted reduction (proven in R1)
// ---------------------------------------------------------------------------
__global__ __launch_bounds__(256) void finalize_kernel(
    const float* __restrict__ seq, float* __restrict__ out) {
    __shared__ float aw[256];
    __shared__ float sbuf[16];
    int b = blockIdx.x;
    int tid = threadIdx.x;
    int lane = tid & 31, warp = tid >> 5;

    float v1 = g_s[tid * 128 + b];
    float v2 = g_s[M_TOT + tid * 128 + b];

    float m1 = v1, m2 = v2;
#pragma unroll
    for (int o = 16; o; o >>= 1) {
        m1 = fmaxf(m1, __shfl_xor_sync(0xffffffffu, m1, o));
        m2 = fmaxf(m2, __shfl_xor_sync(0xffffffffu, m2, o));
    }
    if (lane == 0) { sbuf[warp] = m1; sbuf[8 + warp] = m2; }
    __syncthreads();
    m1 = sbuf[0]; m2 = sbuf[8];
#pragma unroll
    for (int i = 1; i < 8; i++) {
        m1 = fmaxf(m1, sbuf[i]);
        m2 = fmaxf(m2, sbuf[8 + i]);
    }
    float e1 = __expf(v1 - m1), e2 = __expf(v2 - m2);
    __syncthreads();
    float s1 = e1, s2 = e2;
#pragma unroll
    for (int o = 16; o; o >>= 1) {
        s1 += __shfl_xor_sync(0xffffffffu, s1, o);
        s2 += __shfl_xor_sync(0xffffffffu, s2, o);
    }
    if (lane == 0) { sbuf[warp] = s1; sbuf[8 + warp] = s2; }
    __syncthreads();
    s1 = 0.0f; s2 = 0.0f;
#pragma unroll
    for (int i = 0; i < 8; i++) { s1 += sbuf[i]; s2 += sbuf[8 + i]; }
    aw[tid] = (e1 / s1 + e2 / s2) * (0.5f / 256.0f);
    __syncthreads();

    int d = blockIdx.y * 256 + tid;
    const float* p = seq + b * 1024 + d;
    float acc = 0.0f;
#pragma unroll 8
    for (int s = 0; s < 256; s++) acc = fmaf(aw[s], p[(size_t)s * 131072], acc);
    out[b * 1024 + d] = acc;
}

// ---------------------------------------------------------------------------
extern "C" void kernel_launch(void* const* d_in, const int* in_sizes, int n_in,
                              void* d_out, int out_size) {
    const float* f1  = (const float*)d_in[0];
    const float* f2  = (const float*)d_in[1];
    const float* seq = (const float*)d_in[2];
    const float* W11 = (const float*)d_in[3];
    const float* b11 = (const float*)d_in[4];
    const float* W12 = (const float*)d_in[5];
    const float* b12 = (const float*)d_in[6];
    const float* W21 = (const float*)d_in[7];
    // d_in[8]=b21, d_in[10]=b22: softmax-invariant scalar shifts -> dropped
    const float* W22 = (const float*)d_in[9];
    float* out = (float*)d_out;

    cudaFuncSetAttribute(main_kernel, cudaFuncAttributeMaxDynamicSharedMemorySize,
                         SMEM_MAIN);

    convert_kernel<<<2048, 256>>>(seq);
    transpose_kernel<<<dim3(32, 64), 256>>>(W11, W12, b11, b12);
    prepc_kernel<<<256, 256>>>(f1, f2, W11, W12);
    main_kernel<<<dim3(8, 256), 256, SMEM_MAIN>>>(W21, W22);
    finalize_kernel<<<dim3(128, 4), 256>>>(seq, out);
}